// round 1
// baseline (speedup 1.0000x reference)
#include <cuda_runtime.h>

#define NMAX 100000
#define EMAX 800000

// Scratch (static __device__ arrays per allocation rules)
__device__ float g_x64[NMAX * 64];   // x @ Wm + bm
__device__ float g_h[NMAX * 64];     // per-layer transformed features
__device__ float g_agg[NMAX * 64];   // layer-1 output (post relu)
__device__ float g_dinv[NMAX];       // deg accumulator, then rsqrt(deg)
__device__ int   g_cnt[NMAX];        // in-degree (edge count) per node
__device__ int   g_rowptr[NMAX];     // exclusive prefix of g_cnt
__device__ int   g_pos[NMAX];        // fill cursors
__device__ int   g_ssrc[EMAX];       // CSR: source node per (dst-sorted) edge
__device__ float g_snorm[EMAX];      // CSR: norm per (dst-sorted) edge
__device__ int   g_bsum[128];
__device__ int   g_bscan[128];

// ---------------- preprocessing ----------------

__global__ void k_init(int n) {
    int i = blockIdx.x * blockDim.x + threadIdx.x;
    if (i < n) { g_dinv[i] = 1.0f; g_cnt[i] = 0; }  // self-loop weight 1 pre-seeded
}

__global__ void k_deg(const int* __restrict__ src, const int* __restrict__ dst,
                      const float* __restrict__ w, int e) {
    int i = blockIdx.x * blockDim.x + threadIdx.x;
    if (i < e) {
        int d = dst[i];
        atomicAdd(&g_dinv[d], w[i]);
        atomicAdd(&g_cnt[d], 1);
    }
}

__global__ void k_dinv(int n) {
    int i = blockIdx.x * blockDim.x + threadIdx.x;
    if (i < n) g_dinv[i] = rsqrtf(g_dinv[i]);   // deg >= 1 always (self loop)
}

__global__ void k_scan1(int n) {   // 1024 threads/block
    __shared__ int sh[1024];
    int t = threadIdx.x;
    int i = blockIdx.x * 1024 + t;
    int v = (i < n) ? g_cnt[i] : 0;
    sh[t] = v; __syncthreads();
    #pragma unroll
    for (int off = 1; off < 1024; off <<= 1) {
        int x = (t >= off) ? sh[t - off] : 0;
        __syncthreads();
        sh[t] += x;
        __syncthreads();
    }
    if (i < n) g_rowptr[i] = sh[t] - v;          // block-local exclusive
    if (t == 1023) g_bsum[blockIdx.x] = sh[1023];
}

__global__ void k_scan2(int nb) {  // single block of 128
    __shared__ int sh[128];
    int t = threadIdx.x;
    int v = (t < nb) ? g_bsum[t] : 0;
    sh[t] = v; __syncthreads();
    #pragma unroll
    for (int off = 1; off < 128; off <<= 1) {
        int x = (t >= off) ? sh[t - off] : 0;
        __syncthreads();
        sh[t] += x;
        __syncthreads();
    }
    if (t < nb) g_bscan[t] = sh[t] - v;
}

__global__ void k_scan3(int n) {
    int i = blockIdx.x * blockDim.x + threadIdx.x;
    if (i < n) {
        int r = g_rowptr[i] + g_bscan[i >> 10];
        g_rowptr[i] = r;
        g_pos[i] = r;
    }
}

__global__ void k_fill(const int* __restrict__ src, const int* __restrict__ dst,
                       const float* __restrict__ w, int e) {
    int i = blockIdx.x * blockDim.x + threadIdx.x;
    if (i < e) {
        int d = dst[i], s = src[i];
        int p = atomicAdd(&g_pos[d], 1);
        g_ssrc[p] = s;
        g_snorm[p] = g_dinv[s] * w[i] * g_dinv[d];
    }
}

// ---------------- GEMM: C[n,64] = A[n,K] @ W[K,64] (+bias) ----------------
// BM=128, BN=64, BK=16, TM=8, TN=4, 256 threads.

__global__ __launch_bounds__(256)
void k_gemm(const float* __restrict__ A, const float* __restrict__ W,
            const float* __restrict__ bias, float* __restrict__ C,
            int n, int K) {
    __shared__ float As[16][128];
    __shared__ float Bs[16][64];
    int t = threadIdx.x;
    int rowBase = blockIdx.x * 128;
    int ty = t >> 4;          // 0..15 -> 8 rows each
    int tx = t & 15;          // 0..15 -> 4 cols each
    float acc[8][4];
    #pragma unroll
    for (int i = 0; i < 8; i++)
        #pragma unroll
        for (int j = 0; j < 4; j++) acc[i][j] = 0.0f;

    for (int k0 = 0; k0 < K; k0 += 16) {
        // load A tile (128 x 16), transposed into As[k][row]
        #pragma unroll
        for (int l = 0; l < 2; l++) {
            int lin = t + l * 256;          // 0..511
            int r = lin >> 2;               // 0..127
            int c4 = (lin & 3) * 4;         // 0,4,8,12
            int row = rowBase + r;
            float4 v = make_float4(0.f, 0.f, 0.f, 0.f);
            if (row < n) v = *(const float4*)&A[(long)row * K + k0 + c4];
            As[c4 + 0][r] = v.x;
            As[c4 + 1][r] = v.y;
            As[c4 + 2][r] = v.z;
            As[c4 + 3][r] = v.w;
        }
        // load B tile (16 x 64)
        {
            int kr = t >> 4;
            int c = (t & 15) * 4;
            *(float4*)&Bs[kr][c] = *(const float4*)&W[(k0 + kr) * 64 + c];
        }
        __syncthreads();
        #pragma unroll
        for (int kk = 0; kk < 16; kk++) {
            float a[8], b[4];
            #pragma unroll
            for (int i = 0; i < 8; i++) a[i] = As[kk][ty * 8 + i];
            #pragma unroll
            for (int j = 0; j < 4; j++) b[j] = Bs[kk][tx * 4 + j];
            #pragma unroll
            for (int i = 0; i < 8; i++)
                #pragma unroll
                for (int j = 0; j < 4; j++)
                    acc[i][j] += a[i] * b[j];
        }
        __syncthreads();
    }

    float bv[4] = {0.f, 0.f, 0.f, 0.f};
    if (bias) {
        #pragma unroll
        for (int j = 0; j < 4; j++) bv[j] = bias[tx * 4 + j];
    }
    #pragma unroll
    for (int i = 0; i < 8; i++) {
        int row = rowBase + ty * 8 + i;
        if (row < n) {
            float4 o;
            o.x = acc[i][0] + bv[0];
            o.y = acc[i][1] + bv[1];
            o.z = acc[i][2] + bv[2];
            o.w = acc[i][3] + bv[3];
            *(float4*)&C[(long)row * 64 + tx * 4] = o;
        }
    }
}

// ---------------- aggregation: warp per node, float2 per lane ----------------

__global__ void k_agg(const float* __restrict__ h, float* __restrict__ out,
                      const float* __restrict__ bias, int n, int doRelu) {
    int warp = (blockIdx.x * blockDim.x + threadIdx.x) >> 5;
    int lane = threadIdx.x & 31;
    if (warp >= n) return;
    int start = g_rowptr[warp];
    int cnt = g_cnt[warp];
    const float2* hp = (const float2*)h;
    float ax = 0.f, ay = 0.f;
    for (int i = 0; i < cnt; i++) {
        int s = __ldg(&g_ssrc[start + i]);
        float nrm = __ldg(&g_snorm[start + i]);
        float2 v = hp[(long)s * 32 + lane];
        ax += v.x * nrm;
        ay += v.y * nrm;
    }
    // self loop
    float di = g_dinv[warp];
    float sn = di * di;
    float2 sv = hp[(long)warp * 32 + lane];
    ax += sv.x * sn;
    ay += sv.y * sn;
    // bias (+ optional relu)
    ax += bias[lane * 2];
    ay += bias[lane * 2 + 1];
    if (doRelu) { ax = fmaxf(ax, 0.f); ay = fmaxf(ay, 0.f); }
    float2 o; o.x = ax; o.y = ay;
    ((float2*)out)[(long)warp * 32 + lane] = o;
}

// ---------------- launcher ----------------

extern "C" void kernel_launch(void* const* d_in, const int* in_sizes, int n_in,
                              void* d_out, int out_size) {
    const float* x  = (const float*)d_in[0];
    const int*   ei = (const int*)d_in[1];
    const float* w  = (const float*)d_in[2];
    const float* Wm = (const float*)d_in[3];
    const float* bm = (const float*)d_in[4];
    const float* W1 = (const float*)d_in[5];
    const float* b1 = (const float*)d_in[6];
    const float* W2 = (const float*)d_in[7];
    const float* b2 = (const float*)d_in[8];

    int e = in_sizes[2];
    int n = in_sizes[0] / 384;
    const int* src = ei;
    const int* dst = ei + e;

    void *p_x64, *p_h, *p_agg;
    cudaGetSymbolAddress(&p_x64, g_x64);
    cudaGetSymbolAddress(&p_h,   g_h);
    cudaGetSymbolAddress(&p_agg, g_agg);
    float* x64 = (float*)p_x64;
    float* h   = (float*)p_h;
    float* agg = (float*)p_agg;

    int nb = (n + 1023) / 1024;

    // graph preprocessing (CSR + norms), reused by both layers
    k_init<<<(n + 255) / 256, 256>>>(n);
    k_deg<<<(e + 255) / 256, 256>>>(src, dst, w, e);
    k_dinv<<<(n + 255) / 256, 256>>>(n);
    k_scan1<<<nb, 1024>>>(n);
    k_scan2<<<1, 128>>>(nb);
    k_scan3<<<(n + 255) / 256, 256>>>(n);
    k_fill<<<(e + 255) / 256, 256>>>(src, dst, w, e);

    // feature projection: x64 = x @ Wm + bm
    k_gemm<<<(n + 127) / 128, 256>>>(x, Wm, bm, x64, n, 384);

    // layer 1: h = x64 @ W1 ; agg = relu(aggregate(h) + b1)
    k_gemm<<<(n + 127) / 128, 256>>>(x64, W1, nullptr, h, n, 64);
    k_agg<<<(n + 7) / 8, 256>>>(h, agg, b1, n, 1);

    // layer 2: h = agg @ W2 ; out = aggregate(h) + b2
    k_gemm<<<(n + 127) / 128, 256>>>(agg, W2, nullptr, h, n, 64);
    k_agg<<<(n + 7) / 8, 256>>>(h, (float*)d_out, b2, n, 0);
}